// round 1
// baseline (speedup 1.0000x reference)
#include <cuda_runtime.h>
#include <math.h>

#define Bq 256
#define Sq 512
#define Iq 128
#define Hq 256
#define CPG 16      // CTAs per group
#define NGRP 8      // groups
#define GB 32       // batches per group
#define NCTA 128
#define NTHR 256

// ---- global scratch (static device allocs are allowed) ----
__device__ float d_enc[(size_t)Sq * Bq * Hq];   // [S][B][H]  134MB, also h exchange
__device__ float d_scores[Bq * Iq];             // [B][128] tanh'd attention scores
__device__ float d_xwg[Bq * Iq];                // [B][128] alpha * x_t
__device__ int   g_cnt[NGRP];
__device__ int   g_phase[NGRP];

__device__ __forceinline__ int ld_acq(const int* p) {
    int v;
    asm volatile("ld.acquire.gpu.b32 %0, [%1];" : "=r"(v) : "l"(p) : "memory");
    return v;
}
__device__ __forceinline__ void red_release_add(int* p, int v) {
    asm volatile("red.release.gpu.global.add.s32 [%0], %1;" :: "l"(p), "r"(v) : "memory");
}
__device__ __forceinline__ float sigmf(float x) { return 1.f / (1.f + expf(-x)); }

// Group barrier among CPG co-resident CTAs. 'want' only meaningful in tid 0.
__device__ __forceinline__ void group_barrier(int g, int& want) {
    __threadfence();           // release writes of all threads (cumulative via bar)
    __syncthreads();
    if (threadIdx.x == 0) {
        want++;
        int old = atomicAdd(&g_cnt[g], 1);
        if (old == CPG - 1) {
            atomicExch(&g_cnt[g], 0);          // safe: no new arrivals until phase bump
            red_release_add(&g_phase[g], 1);   // release
        } else {
            while (ld_acq(&g_phase[g]) < want) { }
        }
    }
    __syncthreads();
    __threadfence();           // acquire side for all threads
}

// SMEM layout offsets (in floats)
#define O_WA   0        // 8*384   = 3072
#define O_WIH  3072     // 48*128  = 6144
#define O_WHH  9216     // 48*256  = 12288
#define O_BA   21504    // 8
#define O_BIH  21512    // 48
#define O_BHH  21560    // 48
#define O_HS   21608    // 256*33  = 8448
#define O_XTS  30056    // 128*33  = 4224
#define O_XWS  34280    // 128*33  = 4224
#define O_GIS  38504    // 48*33   = 1584
#define O_GHS  40088    // 48*33   = 1584
#define O_RED  41672    // 64
#define SMEM_FLOATS 41736

extern "C" __global__ void __launch_bounds__(NTHR)
da_rnn_kernel(const float* __restrict__ x,
              const float* __restrict__ W_a,  const float* __restrict__ b_a,
              const float* __restrict__ W_ih, const float* __restrict__ b_ih,
              const float* __restrict__ W_hh, const float* __restrict__ b_hh,
              const float* __restrict__ W_t,  const float* __restrict__ b_t,
              const float* __restrict__ W_f,  const float* __restrict__ b_f,
              float* __restrict__ out)
{
    extern __shared__ float sm[];
    float* Wa_s  = sm + O_WA;
    float* Wih_s = sm + O_WIH;
    float* Whh_s = sm + O_WHH;
    float* ba_s  = sm + O_BA;
    float* bih_s = sm + O_BIH;
    float* bhh_s = sm + O_BHH;
    float* hs    = sm + O_HS;    // [256][33]  h transposed [k][b]
    float* xts   = sm + O_XTS;   // [128][33]
    float* xws   = sm + O_XWS;   // [128][33]
    float* gis   = sm + O_GIS;   // [48][33]
    float* ghs   = sm + O_GHS;   // [48][33]
    float* red   = sm + O_RED;

    const int tid  = threadIdx.x;
    const int grp  = blockIdx.x >> 4;     // 0..7
    const int rr   = blockIdx.x & 15;     // 0..15  CTA within group
    const int gb0  = grp * GB;            // first global batch of group
    const int lane = tid & 31;
    const int wrp  = tid >> 5;            // 0..7

    // ---- load weight slice into SMEM (once) ----
    for (int i = tid; i < 8 * 384; i += NTHR)
        Wa_s[i] = W_a[3072 * rr + i];                       // rows 8rr..8rr+7 contiguous
    for (int i = tid; i < 48 * 128; i += NTHR) {
        int l = i >> 7, k = i & 127;
        int grow = (l >> 4) * Hq + 16 * rr + (l & 15);      // gate*256 + unit
        Wih_s[i] = W_ih[grow * Iq + k];
    }
    for (int i = tid; i < 48 * 256; i += NTHR) {
        int l = i >> 8, k = i & 255;
        int grow = (l >> 4) * Hq + 16 * rr + (l & 15);
        Whh_s[i] = W_hh[grow * Hq + k];
    }
    if (tid < 8) ba_s[tid] = b_a[8 * rr + tid];
    if (tid < 48) {
        int grow = (tid >> 4) * Hq + 16 * rr + (tid & 15);
        bih_s[tid] = b_ih[grow];
        bhh_s[tid] = b_hh[grow];
    }

    int want = 0;
    if (tid == 0) want = ld_acq(&g_phase[grp]);   // base phase (monotonic across replays)
    __syncthreads();

    // ================= recurrent loop =================
    for (int t = 0; t < Sq; t++) {
        // ---- load h(t-1) and x_t into transposed SMEM ----
        if (t == 0) {
            for (int i = tid; i < Hq * GB; i += NTHR) {
                int u = i >> 5, b = i & 31;
                hs[u * 33 + b] = 0.f;
            }
        } else {
            const float* ep = d_enc + (size_t)(t - 1) * Bq * Hq + (size_t)gb0 * Hq;
            for (int i = tid; i < Hq * GB; i += NTHR) {
                int b = i >> 8, u = i & 255;
                hs[u * 33 + b] = ep[b * Hq + u];
            }
        }
        for (int i = tid; i < Iq * GB; i += NTHR) {
            int b = i >> 7, k = i & 127;
            xts[k * 33 + b] = x[((size_t)(gb0 + b) * Sq + t) * Iq + k];
        }
        __syncthreads();

        // ---- P1a: scores slice (thread = (row, b)) ----
        {
            int row = wrp;            // 8 rows, warp per row
            int b = lane;
            float acc = ba_s[row];
            const float* wr = Wa_s + row * 384;
            #pragma unroll 4
            for (int k = 0; k < Iq; k += 4) {
                float4 wv = *(const float4*)(wr + k);
                acc += wv.x * xts[k * 33 + b] + wv.y * xts[(k + 1) * 33 + b]
                     + wv.z * xts[(k + 2) * 33 + b] + wv.w * xts[(k + 3) * 33 + b];
            }
            #pragma unroll 4
            for (int k = 0; k < Hq; k += 4) {
                float4 wv = *(const float4*)(wr + Iq + k);
                acc += wv.x * hs[k * 33 + b] + wv.y * hs[(k + 1) * 33 + b]
                     + wv.z * hs[(k + 2) * 33 + b] + wv.w * hs[(k + 3) * 33 + b];
            }
            d_scores[(gb0 + b) * Iq + 8 * rr + row] = tanhf(acc);
        }

        // ---- P1b: gh slice (warp = 6 rows, lane = batch), local only ----
        {
            const int R = 6 * wrp;
            float a0 = bhh_s[R], a1 = bhh_s[R + 1], a2 = bhh_s[R + 2];
            float a3 = bhh_s[R + 3], a4 = bhh_s[R + 4], a5 = bhh_s[R + 5];
            const float* wb = Whh_s + R * Hq;
            #pragma unroll 2
            for (int k = 0; k < Hq; k += 4) {
                float h0 = hs[k * 33 + lane];
                float h1 = hs[(k + 1) * 33 + lane];
                float h2 = hs[(k + 2) * 33 + lane];
                float h3 = hs[(k + 3) * 33 + lane];
                float4 wv;
                wv = *(const float4*)(wb + k);            a0 += wv.x*h0 + wv.y*h1 + wv.z*h2 + wv.w*h3;
                wv = *(const float4*)(wb + 256 + k);      a1 += wv.x*h0 + wv.y*h1 + wv.z*h2 + wv.w*h3;
                wv = *(const float4*)(wb + 512 + k);      a2 += wv.x*h0 + wv.y*h1 + wv.z*h2 + wv.w*h3;
                wv = *(const float4*)(wb + 768 + k);      a3 += wv.x*h0 + wv.y*h1 + wv.z*h2 + wv.w*h3;
                wv = *(const float4*)(wb + 1024 + k);     a4 += wv.x*h0 + wv.y*h1 + wv.z*h2 + wv.w*h3;
                wv = *(const float4*)(wb + 1280 + k);     a5 += wv.x*h0 + wv.y*h1 + wv.z*h2 + wv.w*h3;
            }
            ghs[(R + 0) * 33 + lane] = a0;
            ghs[(R + 1) * 33 + lane] = a1;
            ghs[(R + 2) * 33 + lane] = a2;
            ghs[(R + 3) * 33 + lane] = a3;
            ghs[(R + 4) * 33 + lane] = a4;
            ghs[(R + 5) * 33 + lane] = a5;
        }
        group_barrier(grp, want);   // scores visible group-wide

        // ---- P2: softmax over 128 + xw for this CTA's 2 batches ----
        {
            int half = tid >> 7;            // 0/1
            int i = tid & 127;
            int b = 2 * rr + half;
            int gb = gb0 + b;
            float e = expf(d_scores[gb * Iq + i]);   // scores already tanh'd, bounded
            float s = e;
            #pragma unroll
            for (int off = 16; off; off >>= 1) s += __shfl_xor_sync(0xffffffffu, s, off);
            if (lane == 0) red[wrp] = s;
            __syncthreads();
            float denom = red[half * 4] + red[half * 4 + 1] + red[half * 4 + 2] + red[half * 4 + 3];
            d_xwg[gb * Iq + i] = (e / denom) * xts[i * 33 + b];
        }
        group_barrier(grp, want);   // xw visible group-wide

        // ---- P3: gi slice + gates + h_new ----
        for (int i = tid; i < Iq * GB; i += NTHR) {
            int b = i >> 7, k = i & 127;
            xws[k * 33 + b] = d_xwg[(gb0 + b) * Iq + k];
        }
        __syncthreads();
        {
            const int R = 6 * wrp;
            float a0 = bih_s[R], a1 = bih_s[R + 1], a2 = bih_s[R + 2];
            float a3 = bih_s[R + 3], a4 = bih_s[R + 4], a5 = bih_s[R + 5];
            const float* wb = Wih_s + R * Iq;
            #pragma unroll 2
            for (int k = 0; k < Iq; k += 4) {
                float h0 = xws[k * 33 + lane];
                float h1 = xws[(k + 1) * 33 + lane];
                float h2 = xws[(k + 2) * 33 + lane];
                float h3 = xws[(k + 3) * 33 + lane];
                float4 wv;
                wv = *(const float4*)(wb + k);           a0 += wv.x*h0 + wv.y*h1 + wv.z*h2 + wv.w*h3;
                wv = *(const float4*)(wb + 128 + k);     a1 += wv.x*h0 + wv.y*h1 + wv.z*h2 + wv.w*h3;
                wv = *(const float4*)(wb + 256 + k);     a2 += wv.x*h0 + wv.y*h1 + wv.z*h2 + wv.w*h3;
                wv = *(const float4*)(wb + 384 + k);     a3 += wv.x*h0 + wv.y*h1 + wv.z*h2 + wv.w*h3;
                wv = *(const float4*)(wb + 512 + k);     a4 += wv.x*h0 + wv.y*h1 + wv.z*h2 + wv.w*h3;
                wv = *(const float4*)(wb + 640 + k);     a5 += wv.x*h0 + wv.y*h1 + wv.z*h2 + wv.w*h3;
            }
            gis[(R + 0) * 33 + lane] = a0;
            gis[(R + 1) * 33 + lane] = a1;
            gis[(R + 2) * 33 + lane] = a2;
            gis[(R + 3) * 33 + lane] = a3;
            gis[(R + 4) * 33 + lane] = a4;
            gis[(R + 5) * 33 + lane] = a5;
        }
        __syncthreads();
        {
            #pragma unroll
            for (int p = tid; p < 512; p += NTHR) {
                int u = p >> 5, b = p & 31;
                float r = sigmf(gis[u * 33 + b] + ghs[u * 33 + b]);
                float z = sigmf(gis[(16 + u) * 33 + b] + ghs[(16 + u) * 33 + b]);
                float n = tanhf(gis[(32 + u) * 33 + b] + r * ghs[(32 + u) * 33 + b]);
                float hp = hs[(16 * rr + u) * 33 + b];
                float hn = (1.f - z) * n + z * hp;
                d_enc[((size_t)t * Bq + (gb0 + b)) * Hq + 16 * rr + u] = hn;
            }
        }
        group_barrier(grp, want);   // h(t) visible group-wide
    }

    // ================= temporal attention + FC (barrier-free: 2 batches/CTA) =================
    float* wts = xts;     // reuse
    float* ess = gis;     // reuse, 512 floats
    wts[tid] = W_t[tid];
    const float btv = b_t[0];
    const float bfv = b_f[0];
    __syncthreads();

    for (int bi = 0; bi < 2; bi++) {
        int bb = gb0 + 2 * rr + bi;

        // es[t] = exp(tanh(enc[t,bb,:]·W_t + b_t)) ; warp per t-strip
        for (int tt = wrp; tt < Sq; tt += 8) {
            const float* er = d_enc + ((size_t)tt * Bq + bb) * Hq;
            float s = 0.f;
            #pragma unroll
            for (int j = 0; j < 8; j++) s += er[lane + 32 * j] * wts[lane + 32 * j];
            #pragma unroll
            for (int off = 16; off; off >>= 1) s += __shfl_xor_sync(0xffffffffu, s, off);
            if (lane == 0) ess[tt] = expf(tanhf(s + btv));
        }
        __syncthreads();

        // denom = sum_t es[t]
        float pp = ess[tid] + ess[tid + 256];
        #pragma unroll
        for (int off = 16; off; off >>= 1) pp += __shfl_xor_sync(0xffffffffu, pp, off);
        if (lane == 0) red[wrp] = pp;
        __syncthreads();
        float denom = 0.f;
        #pragma unroll
        for (int j = 0; j < 8; j++) denom += red[j];

        // context[h=tid] = sum_t es[t]*enc[t,bb,tid] / denom
        float acc = 0.f;
        #pragma unroll 4
        for (int tt = 0; tt < Sq; tt++)
            acc += ess[tt] * d_enc[((size_t)tt * Bq + bb) * Hq + tid];
        float ctx = acc / denom;

        // logit = context·W_f + b_f ; out = sigmoid
        float part = ctx * W_f[tid];
        #pragma unroll
        for (int off = 16; off; off >>= 1) part += __shfl_xor_sync(0xffffffffu, part, off);
        __syncthreads();                 // everyone done reading red (denom)
        if (lane == 0) red[wrp] = part;
        __syncthreads();
        if (tid == 0) {
            float lg = bfv;
            #pragma unroll
            for (int j = 0; j < 8; j++) lg += red[j];
            out[bb] = 1.f / (1.f + expf(-lg));
        }
        __syncthreads();                 // protect ess reuse next iteration
    }
}

extern "C" void kernel_launch(void* const* d_in, const int* in_sizes, int n_in,
                              void* d_out, int out_size)
{
    const float* x    = (const float*)d_in[0];
    const float* W_a  = (const float*)d_in[1];
    const float* b_a  = (const float*)d_in[2];
    const float* W_ih = (const float*)d_in[3];
    const float* b_ih = (const float*)d_in[4];
    const float* W_hh = (const float*)d_in[5];
    const float* b_hh = (const float*)d_in[6];
    const float* W_t  = (const float*)d_in[7];
    const float* b_t  = (const float*)d_in[8];
    const float* W_f  = (const float*)d_in[9];
    const float* b_f  = (const float*)d_in[10];

    const size_t smem_bytes = (size_t)SMEM_FLOATS * sizeof(float);  // 166944
    cudaFuncSetAttribute(da_rnn_kernel, cudaFuncAttributeMaxDynamicSharedMemorySize,
                         (int)smem_bytes);
    da_rnn_kernel<<<NCTA, NTHR, smem_bytes>>>(x, W_a, b_a, W_ih, b_ih, W_hh, b_hh,
                                              W_t, b_t, W_f, b_f, (float*)d_out);
}

// round 3
// speedup vs baseline: 1.0002x; 1.0002x over previous
#include <cuda_runtime.h>
#include <math.h>

#define Bq 256
#define Sq 512
#define Iq 128
#define Hq 256
#define CPG 16      // CTAs per group
#define NGRP 8      // groups
#define GB 32       // batches per group
#define NCTA 128
#define NTHR 256

// ---- global scratch (static device allocs are allowed) ----
__device__ float d_enc[(size_t)Sq * Bq * Hq];   // [S][B][H]  134MB, also h exchange
__device__ float d_scores[Bq * Iq];             // [B][128] tanh'd attention scores
__device__ float d_xwg[Bq * Iq];                // [B][128] alpha * x_t
__device__ int   g_cnt[NGRP];
__device__ int   g_phase[NGRP];

__device__ __forceinline__ int ld_acq(const int* p) {
    int v;
    asm volatile("ld.acquire.gpu.b32 %0, [%1];" : "=r"(v) : "l"(p) : "memory");
    return v;
}
__device__ __forceinline__ void red_release_add(int* p, int v) {
    asm volatile("red.release.gpu.global.add.s32 [%0], %1;" :: "l"(p), "r"(v) : "memory");
}
__device__ __forceinline__ float sigmf(float x) { return 1.f / (1.f + expf(-x)); }

// Group barrier among CPG co-resident CTAs. 'want' only meaningful in tid 0.
__device__ __forceinline__ void group_barrier(int g, int& want) {
    __threadfence();           // release writes of all threads (cumulative via bar)
    __syncthreads();
    if (threadIdx.x == 0) {
        want++;
        int old = atomicAdd(&g_cnt[g], 1);
        if (old == CPG - 1) {
            atomicExch(&g_cnt[g], 0);          // safe: no new arrivals until phase bump
            red_release_add(&g_phase[g], 1);   // release
        } else {
            while (ld_acq(&g_phase[g]) < want) { }
        }
    }
    __syncthreads();
    __threadfence();           // acquire side for all threads
}

// SMEM layout offsets (in floats)
#define O_WA   0        // 8*384   = 3072
#define O_WIH  3072     // 48*128  = 6144
#define O_WHH  9216     // 48*256  = 12288
#define O_BA   21504    // 8
#define O_BIH  21512    // 48
#define O_BHH  21560    // 48
#define O_HS   21608    // 256*33  = 8448
#define O_XTS  30056    // 128*33  = 4224
#define O_XWS  34280    // 128*33  = 4224
#define O_GIS  38504    // 48*33   = 1584
#define O_GHS  40088    // 48*33   = 1584
#define O_RED  41672    // 64
#define SMEM_FLOATS 41736

extern "C" __global__ void __launch_bounds__(NTHR)
da_rnn_kernel(const float* __restrict__ x,
              const float* __restrict__ W_a,  const float* __restrict__ b_a,
              const float* __restrict__ W_ih, const float* __restrict__ b_ih,
              const float* __restrict__ W_hh, const float* __restrict__ b_hh,
              const float* __restrict__ W_t,  const float* __restrict__ b_t,
              const float* __restrict__ W_f,  const float* __restrict__ b_f,
              float* __restrict__ out)
{
    extern __shared__ float sm[];
    float* Wa_s  = sm + O_WA;
    float* Wih_s = sm + O_WIH;
    float* Whh_s = sm + O_WHH;
    float* ba_s  = sm + O_BA;
    float* bih_s = sm + O_BIH;
    float* bhh_s = sm + O_BHH;
    float* hs    = sm + O_HS;    // [256][33]  h transposed [k][b]
    float* xts   = sm + O_XTS;   // [128][33]
    float* xws   = sm + O_XWS;   // [128][33]
    float* gis   = sm + O_GIS;   // [48][33]
    float* ghs   = sm + O_GHS;   // [48][33]
    float* red   = sm + O_RED;

    const int tid  = threadIdx.x;
    const int grp  = blockIdx.x >> 4;     // 0..7
    const int rr   = blockIdx.x & 15;     // 0..15  CTA within group
    const int gb0  = grp * GB;            // first global batch of group
    const int lane = tid & 31;
    const int wrp  = tid >> 5;            // 0..7

    // ---- load weight slice into SMEM (once) ----
    for (int i = tid; i < 8 * 384; i += NTHR)
        Wa_s[i] = W_a[3072 * rr + i];                       // rows 8rr..8rr+7 contiguous
    for (int i = tid; i < 48 * 128; i += NTHR) {
        int l = i >> 7, k = i & 127;
        int grow = (l >> 4) * Hq + 16 * rr + (l & 15);      // gate*256 + unit
        Wih_s[i] = W_ih[grow * Iq + k];
    }
    for (int i = tid; i < 48 * 256; i += NTHR) {
        int l = i >> 8, k = i & 255;
        int grow = (l >> 4) * Hq + 16 * rr + (l & 15);
        Whh_s[i] = W_hh[grow * Hq + k];
    }
    if (tid < 8) ba_s[tid] = b_a[8 * rr + tid];
    if (tid < 48) {
        int grow = (tid >> 4) * Hq + 16 * rr + (tid & 15);
        bih_s[tid] = b_ih[grow];
        bhh_s[tid] = b_hh[grow];
    }

    int want = 0;
    if (tid == 0) want = ld_acq(&g_phase[grp]);   // base phase (monotonic across replays)
    __syncthreads();

    // ================= recurrent loop =================
    for (int t = 0; t < Sq; t++) {
        // ---- load h(t-1) and x_t into transposed SMEM ----
        if (t == 0) {
            for (int i = tid; i < Hq * GB; i += NTHR) {
                int u = i >> 5, b = i & 31;
                hs[u * 33 + b] = 0.f;
            }
        } else {
            const float* ep = d_enc + (size_t)(t - 1) * Bq * Hq + (size_t)gb0 * Hq;
            for (int i = tid; i < Hq * GB; i += NTHR) {
                int b = i >> 8, u = i & 255;
                hs[u * 33 + b] = ep[b * Hq + u];
            }
        }
        for (int i = tid; i < Iq * GB; i += NTHR) {
            int b = i >> 7, k = i & 127;
            xts[k * 33 + b] = x[((size_t)(gb0 + b) * Sq + t) * Iq + k];
        }
        __syncthreads();

        // ---- P1a: scores slice (thread = (row, b)) ----
        {
            int row = wrp;            // 8 rows, warp per row
            int b = lane;
            float acc = ba_s[row];
            const float* wr = Wa_s + row * 384;
            #pragma unroll 4
            for (int k = 0; k < Iq; k += 4) {
                float4 wv = *(const float4*)(wr + k);
                acc += wv.x * xts[k * 33 + b] + wv.y * xts[(k + 1) * 33 + b]
                     + wv.z * xts[(k + 2) * 33 + b] + wv.w * xts[(k + 3) * 33 + b];
            }
            #pragma unroll 4
            for (int k = 0; k < Hq; k += 4) {
                float4 wv = *(const float4*)(wr + Iq + k);
                acc += wv.x * hs[k * 33 + b] + wv.y * hs[(k + 1) * 33 + b]
                     + wv.z * hs[(k + 2) * 33 + b] + wv.w * hs[(k + 3) * 33 + b];
            }
            d_scores[(gb0 + b) * Iq + 8 * rr + row] = tanhf(acc);
        }

        // ---- P1b: gh slice (warp = 6 rows, lane = batch), local only ----
        {
            const int R = 6 * wrp;
            float a0 = bhh_s[R], a1 = bhh_s[R + 1], a2 = bhh_s[R + 2];
            float a3 = bhh_s[R + 3], a4 = bhh_s[R + 4], a5 = bhh_s[R + 5];
            const float* wb = Whh_s + R * Hq;
            #pragma unroll 2
            for (int k = 0; k < Hq; k += 4) {
                float h0 = hs[k * 33 + lane];
                float h1 = hs[(k + 1) * 33 + lane];
                float h2 = hs[(k + 2) * 33 + lane];
                float h3 = hs[(k + 3) * 33 + lane];
                float4 wv;
                wv = *(const float4*)(wb + k);            a0 += wv.x*h0 + wv.y*h1 + wv.z*h2 + wv.w*h3;
                wv = *(const float4*)(wb + 256 + k);      a1 += wv.x*h0 + wv.y*h1 + wv.z*h2 + wv.w*h3;
                wv = *(const float4*)(wb + 512 + k);      a2 += wv.x*h0 + wv.y*h1 + wv.z*h2 + wv.w*h3;
                wv = *(const float4*)(wb + 768 + k);      a3 += wv.x*h0 + wv.y*h1 + wv.z*h2 + wv.w*h3;
                wv = *(const float4*)(wb + 1024 + k);     a4 += wv.x*h0 + wv.y*h1 + wv.z*h2 + wv.w*h3;
                wv = *(const float4*)(wb + 1280 + k);     a5 += wv.x*h0 + wv.y*h1 + wv.z*h2 + wv.w*h3;
            }
            ghs[(R + 0) * 33 + lane] = a0;
            ghs[(R + 1) * 33 + lane] = a1;
            ghs[(R + 2) * 33 + lane] = a2;
            ghs[(R + 3) * 33 + lane] = a3;
            ghs[(R + 4) * 33 + lane] = a4;
            ghs[(R + 5) * 33 + lane] = a5;
        }
        group_barrier(grp, want);   // scores visible group-wide

        // ---- P2: softmax over 128 + xw for this CTA's 2 batches ----
        {
            int half = tid >> 7;            // 0/1
            int i = tid & 127;
            int b = 2 * rr + half;
            int gb = gb0 + b;
            float e = expf(d_scores[gb * Iq + i]);   // scores already tanh'd, bounded
            float s = e;
            #pragma unroll
            for (int off = 16; off; off >>= 1) s += __shfl_xor_sync(0xffffffffu, s, off);
            if (lane == 0) red[wrp] = s;
            __syncthreads();
            float denom = red[half * 4] + red[half * 4 + 1] + red[half * 4 + 2] + red[half * 4 + 3];
            d_xwg[gb * Iq + i] = (e / denom) * xts[i * 33 + b];
        }
        group_barrier(grp, want);   // xw visible group-wide

        // ---- P3: gi slice + gates + h_new ----
        for (int i = tid; i < Iq * GB; i += NTHR) {
            int b = i >> 7, k = i & 127;
            xws[k * 33 + b] = d_xwg[(gb0 + b) * Iq + k];
        }
        __syncthreads();
        {
            const int R = 6 * wrp;
            float a0 = bih_s[R], a1 = bih_s[R + 1], a2 = bih_s[R + 2];
            float a3 = bih_s[R + 3], a4 = bih_s[R + 4], a5 = bih_s[R + 5];
            const float* wb = Wih_s + R * Iq;
            #pragma unroll 2
            for (int k = 0; k < Iq; k += 4) {
                float h0 = xws[k * 33 + lane];
                float h1 = xws[(k + 1) * 33 + lane];
                float h2 = xws[(k + 2) * 33 + lane];
                float h3 = xws[(k + 3) * 33 + lane];
                float4 wv;
                wv = *(const float4*)(wb + k);           a0 += wv.x*h0 + wv.y*h1 + wv.z*h2 + wv.w*h3;
                wv = *(const float4*)(wb + 128 + k);     a1 += wv.x*h0 + wv.y*h1 + wv.z*h2 + wv.w*h3;
                wv = *(const float4*)(wb + 256 + k);     a2 += wv.x*h0 + wv.y*h1 + wv.z*h2 + wv.w*h3;
                wv = *(const float4*)(wb + 384 + k);     a3 += wv.x*h0 + wv.y*h1 + wv.z*h2 + wv.w*h3;
                wv = *(const float4*)(wb + 512 + k);     a4 += wv.x*h0 + wv.y*h1 + wv.z*h2 + wv.w*h3;
                wv = *(const float4*)(wb + 640 + k);     a5 += wv.x*h0 + wv.y*h1 + wv.z*h2 + wv.w*h3;
            }
            gis[(R + 0) * 33 + lane] = a0;
            gis[(R + 1) * 33 + lane] = a1;
            gis[(R + 2) * 33 + lane] = a2;
            gis[(R + 3) * 33 + lane] = a3;
            gis[(R + 4) * 33 + lane] = a4;
            gis[(R + 5) * 33 + lane] = a5;
        }
        __syncthreads();
        {
            #pragma unroll
            for (int p = tid; p < 512; p += NTHR) {
                int u = p >> 5, b = p & 31;
                float r = sigmf(gis[u * 33 + b] + ghs[u * 33 + b]);
                float z = sigmf(gis[(16 + u) * 33 + b] + ghs[(16 + u) * 33 + b]);
                float n = tanhf(gis[(32 + u) * 33 + b] + r * ghs[(32 + u) * 33 + b]);
                float hp = hs[(16 * rr + u) * 33 + b];
                float hn = (1.f - z) * n + z * hp;
                d_enc[((size_t)t * Bq + (gb0 + b)) * Hq + 16 * rr + u] = hn;
            }
        }
        group_barrier(grp, want);   // h(t) visible group-wide
    }

    // ================= temporal attention + FC (barrier-free: 2 batches/CTA) =================
    float* wts = xts;     // reuse
    float* ess = gis;     // reuse, 512 floats
    wts[tid] = W_t[tid];
    const float btv = b_t[0];
    const float bfv = b_f[0];
    __syncthreads();

    for (int bi = 0; bi < 2; bi++) {
        int bb = gb0 + 2 * rr + bi;

        // es[t] = exp(tanh(enc[t,bb,:]·W_t + b_t)) ; warp per t-strip
        for (int tt = wrp; tt < Sq; tt += 8) {
            const float* er = d_enc + ((size_t)tt * Bq + bb) * Hq;
            float s = 0.f;
            #pragma unroll
            for (int j = 0; j < 8; j++) s += er[lane + 32 * j] * wts[lane + 32 * j];
            #pragma unroll
            for (int off = 16; off; off >>= 1) s += __shfl_xor_sync(0xffffffffu, s, off);
            if (lane == 0) ess[tt] = expf(tanhf(s + btv));
        }
        __syncthreads();

        // denom = sum_t es[t]
        float pp = ess[tid] + ess[tid + 256];
        #pragma unroll
        for (int off = 16; off; off >>= 1) pp += __shfl_xor_sync(0xffffffffu, pp, off);
        if (lane == 0) red[wrp] = pp;
        __syncthreads();
        float denom = 0.f;
        #pragma unroll
        for (int j = 0; j < 8; j++) denom += red[j];

        // context[h=tid] = sum_t es[t]*enc[t,bb,tid] / denom
        float acc = 0.f;
        #pragma unroll 4
        for (int tt = 0; tt < Sq; tt++)
            acc += ess[tt] * d_enc[((size_t)tt * Bq + bb) * Hq + tid];
        float ctx = acc / denom;

        // logit = context·W_f + b_f ; out = sigmoid
        float part = ctx * W_f[tid];
        #pragma unroll
        for (int off = 16; off; off >>= 1) part += __shfl_xor_sync(0xffffffffu, part, off);
        __syncthreads();                 // everyone done reading red (denom)
        if (lane == 0) red[wrp] = part;
        __syncthreads();
        if (tid == 0) {
            float lg = bfv;
            #pragma unroll
            for (int j = 0; j < 8; j++) lg += red[j];
            out[bb] = 1.f / (1.f + expf(-lg));
        }
        __syncthreads();                 // protect ess reuse next iteration
    }
}

extern "C" void kernel_launch(void* const* d_in, const int* in_sizes, int n_in,
                              void* d_out, int out_size)
{
    const float* x    = (const float*)d_in[0];
    const float* W_a  = (const float*)d_in[1];
    const float* b_a  = (const float*)d_in[2];
    const float* W_ih = (const float*)d_in[3];
    const float* b_ih = (const float*)d_in[4];
    const float* W_hh = (const float*)d_in[5];
    const float* b_hh = (const float*)d_in[6];
    const float* W_t  = (const float*)d_in[7];
    const float* b_t  = (const float*)d_in[8];
    const float* W_f  = (const float*)d_in[9];
    const float* b_f  = (const float*)d_in[10];

    const size_t smem_bytes = (size_t)SMEM_FLOATS * sizeof(float);  // 166944
    cudaFuncSetAttribute(da_rnn_kernel, cudaFuncAttributeMaxDynamicSharedMemorySize,
                         (int)smem_bytes);
    da_rnn_kernel<<<NCTA, NTHR, smem_bytes>>>(x, W_a, b_a, W_ih, b_ih, W_hh, b_hh,
                                              W_t, b_t, W_f, b_f, (float*)d_out);
}

// round 7
// speedup vs baseline: 1.4044x; 1.4041x over previous
#include <cuda_runtime.h>
#include <math.h>

#define Bq 256
#define Sq 512
#define Iq 128
#define Hq 256
#define CPG 16      // CTAs per group
#define NGRP 8      // groups
#define GB 32       // batches per group
#define NCTA 128
#define NTHR 512

typedef unsigned long long u64;

// ---- global scratch (static device allocs are allowed) ----
__device__ float d_enc[(size_t)Sq * Bq * Hq];   // [S][B][H], also h exchange
__device__ float d_scores[Bq * Iq];             // [B][128] tanh'd attention scores
__device__ int   g_cnt[NGRP];
__device__ int   g_phase[NGRP];

__device__ __forceinline__ int ld_acq(const int* p) {
    int v;
    asm volatile("ld.acquire.gpu.b32 %0, [%1];" : "=r"(v) : "l"(p) : "memory");
    return v;
}
__device__ __forceinline__ void red_release_add(int* p, int v) {
    asm volatile("red.release.gpu.global.add.s32 [%0], %1;" :: "l"(p), "r"(v) : "memory");
}
__device__ __forceinline__ float sigmf(float x) { return 1.f / (1.f + expf(-x)); }

// packed f32x2 FMA: d.lo += a.lo*b.lo ; d.hi += a.hi*b.hi
__device__ __forceinline__ void fma2(u64& d, u64 a, u64 b) {
    asm("fma.rn.f32x2 %0, %1, %2, %0;" : "+l"(d) : "l"(a), "l"(b));
}
__device__ __forceinline__ float f2sum(u64 a, float bias) {
    float lo, hi;
    asm("mov.b64 {%0,%1}, %2;" : "=f"(lo), "=f"(hi) : "l"(a));
    return lo + hi + bias;
}

// Group barrier among CPG co-resident CTAs. 'want' only meaningful in tid 0.
// The gpu-scope __threadfence also flushes L1D (CCTL.IVALL) -> post-barrier
// global reads (d_scores, d_enc) can't hit stale L1 lines.
__device__ __forceinline__ void group_barrier(int g, int& want) {
    __threadfence();
    __syncthreads();
    if (threadIdx.x == 0) {
        want++;
        int old = atomicAdd(&g_cnt[g], 1);
        if (old == CPG - 1) {
            atomicExch(&g_cnt[g], 0);
            red_release_add(&g_phase[g], 1);
        } else {
            while (ld_acq(&g_phase[g]) < want) { }
        }
    }
    __syncthreads();
    __threadfence();
}

// SMEM layout offsets (in floats)
#define O_WA   0        // 8*384   = 3072
#define O_WIH  3072     // 48*128  = 6144
#define O_WHH  9216     // 48*256  = 12288
#define O_BA   21504    // 8
#define O_BIH  21512    // 48
#define O_BHH  21560    // 48
#define O_HS   21608    // 128*33 float2 = 8448 floats  h paired [k2][b]{even,odd}
#define O_XTS  30056    // 64*33 float2  = 4224
#define O_XWS  34280    // 64*33 float2  = 4224
#define O_GIS  38504    // 48*33   = 1584
#define O_GHS  40088    // 48*33   = 1584
#define O_RED  41672    // 32
#define SMEM_FLOATS 41704

extern "C" __global__ void __launch_bounds__(NTHR)
da_rnn_kernel(const float* __restrict__ x,
              const float* __restrict__ W_a,  const float* __restrict__ b_a,
              const float* __restrict__ W_ih, const float* __restrict__ b_ih,
              const float* __restrict__ W_hh, const float* __restrict__ b_hh,
              const float* __restrict__ W_t,  const float* __restrict__ b_t,
              const float* __restrict__ W_f,  const float* __restrict__ b_f,
              float* __restrict__ out)
{
    extern __shared__ float sm[];
    float* Wa_s  = sm + O_WA;
    float* Wih_s = sm + O_WIH;
    float* Whh_s = sm + O_WHH;
    float* ba_s  = sm + O_BA;
    float* bih_s = sm + O_BIH;
    float* bhh_s = sm + O_BHH;
    float* hsf   = sm + O_HS;    // paired: elem(k,b) at ((k>>1)*33+b)*2+(k&1)
    float* xtf   = sm + O_XTS;
    float* xwf   = sm + O_XWS;
    float* gis   = sm + O_GIS;   // [48][33]
    float* ghs   = sm + O_GHS;   // [48][33]
    float* red   = sm + O_RED;
    const u64* hs64 = (const u64*)hsf;   // [k2*33 + b]
    const u64* xt64 = (const u64*)xtf;
    const u64* xw64 = (const u64*)xwf;

    const int tid  = threadIdx.x;
    const int grp  = blockIdx.x >> 4;     // 0..7
    const int rr   = blockIdx.x & 15;     // 0..15
    const int gb0  = grp * GB;
    const int lane = tid & 31;
    const int wrp  = tid >> 5;            // 0..15

    // ---- load weight slice into SMEM (once) ----
    for (int i = tid; i < 8 * 384; i += NTHR)
        Wa_s[i] = W_a[3072 * rr + i];
    for (int i = tid; i < 48 * 128; i += NTHR) {
        int l = i >> 7, k = i & 127;
        int grow = (l >> 4) * Hq + 16 * rr + (l & 15);
        Wih_s[i] = W_ih[grow * Iq + k];
    }
    for (int i = tid; i < 48 * 256; i += NTHR) {
        int l = i >> 8, k = i & 255;
        int grow = (l >> 4) * Hq + 16 * rr + (l & 15);
        Whh_s[i] = W_hh[grow * Hq + k];
    }
    if (tid < 8) ba_s[tid] = b_a[8 * rr + tid];
    if (tid < 48) {
        int grow = (tid >> 4) * Hq + 16 * rr + (tid & 15);
        bih_s[tid] = b_ih[grow];
        bhh_s[tid] = b_hh[grow];
    }

    int want = 0;
    if (tid == 0) want = ld_acq(&g_phase[grp]);
    __syncthreads();

    // ================= recurrent loop =================
    for (int t = 0; t < Sq; t++) {
        // ---- stage h(t-1), x_t into paired SMEM ----
        if (t == 0) {
            for (int i = tid; i < Hq * GB; i += NTHR) {
                int b = i >> 8, u = i & 255;
                hsf[((u >> 1) * 33 + b) * 2 + (u & 1)] = 0.f;
            }
        } else {
            const float* ep = d_enc + (size_t)(t - 1) * Bq * Hq + (size_t)gb0 * Hq;
            for (int i = tid; i < Hq * GB; i += NTHR) {
                int b = i >> 8, u = i & 255;
                hsf[((u >> 1) * 33 + b) * 2 + (u & 1)] = ep[b * Hq + u];
            }
        }
        for (int i = tid; i < Iq * GB; i += NTHR) {
            int b = i >> 7, k = i & 127;
            xtf[((k >> 1) * 33 + b) * 2 + (k & 1)] = x[((size_t)(gb0 + b) * Sq + t) * Iq + k];
        }
        __syncthreads();

        // ---- P1: scores slice + gh slice (h loads shared in warps 0-7) ----
        if (wrp < 8) {
            const int srow = wrp;           // scores row
            const int R = 2 * wrp;          // gh rows R, R+1 (local l=0..15)
            const u64* wax = (const u64*)(Wa_s + srow * 384);
            u64 sacc = 0ull;
            #pragma unroll 4
            for (int k2 = 0; k2 < 64; k2 += 2) {
                u64 x0 = xt64[k2 * 33 + lane];
                u64 x1 = xt64[(k2 + 1) * 33 + lane];
                ulonglong2 w = *(const ulonglong2*)(wax + k2);
                fma2(sacc, w.x, x0); fma2(sacc, w.y, x1);
            }
            const u64* wah = wax + 64;
            const u64* wg0 = (const u64*)(Whh_s + R * Hq);
            const u64* wg1 = wg0 + 128;
            u64 a0 = 0ull, a1 = 0ull;
            #pragma unroll 2
            for (int k2 = 0; k2 < 128; k2 += 2) {
                u64 h0 = hs64[k2 * 33 + lane];
                u64 h1 = hs64[(k2 + 1) * 33 + lane];
                ulonglong2 wa = *(const ulonglong2*)(wah + k2);
                fma2(sacc, wa.x, h0); fma2(sacc, wa.y, h1);
                ulonglong2 w0 = *(const ulonglong2*)(wg0 + k2);
                fma2(a0, w0.x, h0); fma2(a0, w0.y, h1);
                ulonglong2 w1 = *(const ulonglong2*)(wg1 + k2);
                fma2(a1, w1.x, h0); fma2(a1, w1.y, h1);
            }
            d_scores[(gb0 + lane) * Iq + 8 * rr + srow] = tanhf(f2sum(sacc, ba_s[srow]));
            ghs[R * 33 + lane]       = f2sum(a0, bhh_s[R]);
            ghs[(R + 1) * 33 + lane] = f2sum(a1, bhh_s[R + 1]);
        } else {
            const int R = 16 + 4 * (wrp - 8);   // gh rows R..R+3 (l=16..47)
            const u64* w0 = (const u64*)(Whh_s + R * Hq);
            const u64* w1 = w0 + 128;
            const u64* w2 = w0 + 256;
            const u64* w3 = w0 + 384;
            u64 a0 = 0ull, a1 = 0ull, a2 = 0ull, a3 = 0ull;
            #pragma unroll 2
            for (int k2 = 0; k2 < 128; k2 += 2) {
                u64 h0 = hs64[k2 * 33 + lane];
                u64 h1 = hs64[(k2 + 1) * 33 + lane];
                ulonglong2 v0 = *(const ulonglong2*)(w0 + k2);
                fma2(a0, v0.x, h0); fma2(a0, v0.y, h1);
                ulonglong2 v1 = *(const ulonglong2*)(w1 + k2);
                fma2(a1, v1.x, h0); fma2(a1, v1.y, h1);
                ulonglong2 v2 = *(const ulonglong2*)(w2 + k2);
                fma2(a2, v2.x, h0); fma2(a2, v2.y, h1);
                ulonglong2 v3 = *(const ulonglong2*)(w3 + k2);
                fma2(a3, v3.x, h0); fma2(a3, v3.y, h1);
            }
            ghs[R * 33 + lane]       = f2sum(a0, bhh_s[R]);
            ghs[(R + 1) * 33 + lane] = f2sum(a1, bhh_s[R + 1]);
            ghs[(R + 2) * 33 + lane] = f2sum(a2, bhh_s[R + 2]);
            ghs[(R + 3) * 33 + lane] = f2sum(a3, bhh_s[R + 3]);
        }
        group_barrier(grp, want);   // scores visible group-wide

        // ---- P2: softmax + xw for ALL 32 batches, locally (no 2nd barrier) ----
        #pragma unroll
        for (int bi = 0; bi < 2; bi++) {
            int b = 2 * wrp + bi;
            const float* sp = d_scores + (size_t)(gb0 + b) * Iq;
            float e0 = expf(sp[lane]);
            float e1 = expf(sp[lane + 32]);
            float e2 = expf(sp[lane + 64]);
            float e3 = expf(sp[lane + 96]);
            float s = e0 + e1 + e2 + e3;
            #pragma unroll
            for (int off = 16; off; off >>= 1) s += __shfl_xor_sync(0xffffffffu, s, off);
            float inv = 1.f / s;
            int k = lane;
            xwf[((k >> 1) * 33 + b) * 2 + (k & 1)] = e0 * inv * xtf[((k >> 1) * 33 + b) * 2 + (k & 1)];
            k = lane + 32;
            xwf[((k >> 1) * 33 + b) * 2 + (k & 1)] = e1 * inv * xtf[((k >> 1) * 33 + b) * 2 + (k & 1)];
            k = lane + 64;
            xwf[((k >> 1) * 33 + b) * 2 + (k & 1)] = e2 * inv * xtf[((k >> 1) * 33 + b) * 2 + (k & 1)];
            k = lane + 96;
            xwf[((k >> 1) * 33 + b) * 2 + (k & 1)] = e3 * inv * xtf[((k >> 1) * 33 + b) * 2 + (k & 1)];
        }
        __syncthreads();

        // ---- P3: gi slice (3 rows/warp) ----
        {
            const int R = 3 * wrp;
            const u64* w0 = (const u64*)(Wih_s + R * Iq);
            const u64* w1 = w0 + 64;
            const u64* w2 = w0 + 128;
            u64 a0 = 0ull, a1 = 0ull, a2 = 0ull;
            #pragma unroll 4
            for (int k2 = 0; k2 < 64; k2 += 2) {
                u64 x0 = xw64[k2 * 33 + lane];
                u64 x1 = xw64[(k2 + 1) * 33 + lane];
                ulonglong2 v0 = *(const ulonglong2*)(w0 + k2);
                fma2(a0, v0.x, x0); fma2(a0, v0.y, x1);
                ulonglong2 v1 = *(const ulonglong2*)(w1 + k2);
                fma2(a1, v1.x, x0); fma2(a1, v1.y, x1);
                ulonglong2 v2 = *(const ulonglong2*)(w2 + k2);
                fma2(a2, v2.x, x0); fma2(a2, v2.y, x1);
            }
            gis[R * 33 + lane]       = f2sum(a0, bih_s[R]);
            gis[(R + 1) * 33 + lane] = f2sum(a1, bih_s[R + 1]);
            gis[(R + 2) * 33 + lane] = f2sum(a2, bih_s[R + 2]);
        }
        __syncthreads();

        // ---- gates + h_new (coalesced store: u fastest) ----
        {
            int u = tid & 15;
            int b = tid >> 4;
            float r = sigmf(gis[u * 33 + b] + ghs[u * 33 + b]);
            float z = sigmf(gis[(16 + u) * 33 + b] + ghs[(16 + u) * 33 + b]);
            float n = tanhf(gis[(32 + u) * 33 + b] + r * ghs[(32 + u) * 33 + b]);
            int ug = 16 * rr + u;
            float hp = hsf[((ug >> 1) * 33 + b) * 2 + (ug & 1)];
            float hn = (1.f - z) * n + z * hp;
            d_enc[((size_t)t * Bq + gb0 + b) * Hq + ug] = hn;
        }
        group_barrier(grp, want);   // h(t) visible group-wide
    }

    // ================= temporal attention + FC (2 batches/CTA, no group barriers) ==========
    float* wts = xtf;     // 256 floats
    float* ess = gis;     // 512 floats
    float* prt = ghs;     // 512 floats
    if (tid < Hq) wts[tid] = W_t[tid];
    const float btv = b_t[0];
    const float bfv = b_f[0];
    __syncthreads();

    for (int bi = 0; bi < 2; bi++) {
        int bb = gb0 + 2 * rr + bi;

        // es[t] = exp(tanh(enc[t,bb,:]·W_t + b_t))
        for (int tt = wrp; tt < Sq; tt += 16) {
            const float* er = d_enc + ((size_t)tt * Bq + bb) * Hq;
            float s = 0.f;
            #pragma unroll
            for (int j = 0; j < 8; j++) s += er[lane + 32 * j] * wts[lane + 32 * j];
            #pragma unroll
            for (int off = 16; off; off >>= 1) s += __shfl_xor_sync(0xffffffffu, s, off);
            if (lane == 0) ess[tt] = expf(tanhf(s + btv));
        }
        __syncthreads();

        // denom = sum_t es[t]
        float pp = ess[tid];
        #pragma unroll
        for (int off = 16; off; off >>= 1) pp += __shfl_xor_sync(0xffffffffu, pp, off);
        if (lane == 0) red[wrp] = pp;
        __syncthreads();
        float denom = 0.f;
        #pragma unroll
        for (int j = 0; j < 16; j++) denom += red[j];

        // context partial: half the t-range per thread
        {
            int h = tid & 255, half = tid >> 8;
            const float* eb = d_enc + ((size_t)(half * 256) * Bq + bb) * Hq + h;
            const float* ep = ess + half * 256;
            float acc = 0.f;
            #pragma unroll 4
            for (int tt = 0; tt < 256; tt++)
                acc += ep[tt] * eb[(size_t)tt * Bq * Hq];
            prt[tid] = acc;
        }
        __syncthreads();

        if (tid < Hq) {
            float ctx = (prt[tid] + prt[tid + 256]) / denom;
            float part = ctx * W_f[tid];
            #pragma unroll
            for (int off = 16; off; off >>= 1) part += __shfl_xor_sync(0xffffffffu, part, off);
            if (lane == 0) red[16 + wrp] = part;
        }
        __syncthreads();
        if (tid == 0) {
            float lg = bfv;
            #pragma unroll
            for (int j = 0; j < 8; j++) lg += red[16 + j];
            out[bb] = 1.f / (1.f + expf(-lg));
        }
        __syncthreads();
    }
}

extern "C" void kernel_launch(void* const* d_in, const int* in_sizes, int n_in,
                              void* d_out, int out_size)
{
    const float* x    = (const float*)d_in[0];
    const float* W_a  = (const float*)d_in[1];
    const float* b_a  = (const float*)d_in[2];
    const float* W_ih = (const float*)d_in[3];
    const float* b_ih = (const float*)d_in[4];
    const float* W_hh = (const float*)d_in[5];
    const float* b_hh = (const float*)d_in[6];
    const float* W_t  = (const float*)d_in[7];
    const float* b_t  = (const float*)d_in[8];
    const float* W_f  = (const float*)d_in[9];
    const float* b_f  = (const float*)d_in[10];

    const size_t smem_bytes = (size_t)SMEM_FLOATS * sizeof(float);  // 166816
    cudaFuncSetAttribute(da_rnn_kernel, cudaFuncAttributeMaxDynamicSharedMemorySize,
                         (int)smem_bytes);
    da_rnn_kernel<<<NCTA, NTHR, smem_bytes>>>(x, W_a, b_a, W_ih, b_ih, W_hh, b_hh,
                                              W_t, b_t, W_f, b_f, (float*)d_out);
}

// round 8
// speedup vs baseline: 1.4062x; 1.0013x over previous
#include <cuda_runtime.h>
#include <math.h>
#include <stdint.h>

#define Bq 256
#define Sq 512
#define Iq 128
#define Hq 256
#define CPG 16      // CTAs per group/cluster
#define NGRP 8      // groups
#define GB 32       // batches per group
#define NCTA 128
#define NTHR 512

typedef unsigned long long u64;

// ---- global scratch ----
__device__ float d_enc[(size_t)Sq * Bq * Hq];   // [S][B][H] (write-only during loop)
__device__ float d_scores[Bq * Iq];             // fallback path only
__device__ int   g_cnt[NGRP];                   // fallback path only
__device__ int   g_phase[NGRP];                 // fallback path only

// ------------------------------- helpers -----------------------------------
__device__ __forceinline__ int ld_acq(const int* p) {
    int v;
    asm volatile("ld.acquire.gpu.b32 %0, [%1];" : "=r"(v) : "l"(p) : "memory");
    return v;
}
__device__ __forceinline__ void red_release_add(int* p, int v) {
    asm volatile("red.release.gpu.global.add.s32 [%0], %1;" :: "l"(p), "r"(v) : "memory");
}
__device__ __forceinline__ void fma2(u64& d, u64 a, u64 b) {
    asm("fma.rn.f32x2 %0, %1, %2, %0;" : "+l"(d) : "l"(a), "l"(b));
}
__device__ __forceinline__ float f2sum(u64 a, float bias) {
    float lo, hi;
    asm("mov.b64 {%0,%1}, %2;" : "=f"(lo), "=f"(hi) : "l"(a));
    return lo + hi + bias;
}
__device__ __forceinline__ float fsig(float x)  { return 1.f / (1.f + __expf(-x)); }
__device__ __forceinline__ float ftanh(float x) { return 1.f - 2.f / (__expf(2.f * x) + 1.f); }

__device__ __forceinline__ uint32_t smem_u32(const void* p) {
    uint32_t a;
    asm("{ .reg .u64 t; cvta.to.shared.u64 t, %1; cvt.u32.u64 %0, t; }" : "=r"(a) : "l"(p));
    return a;
}
__device__ __forceinline__ void push_b64(uint32_t laddr, int rank, u64 v) {
    uint32_t ra;
    asm volatile("mapa.shared::cluster.u32 %0, %1, %2;" : "=r"(ra) : "r"(laddr), "r"(rank));
    asm volatile("st.shared::cluster.b64 [%0], %1;" :: "r"(ra), "l"(v) : "memory");
}
__device__ __forceinline__ void push_b32(uint32_t laddr, int rank, float v) {
    uint32_t ra;
    asm volatile("mapa.shared::cluster.u32 %0, %1, %2;" : "=r"(ra) : "r"(laddr), "r"(rank));
    asm volatile("st.shared::cluster.f32 [%0], %1;" :: "r"(ra), "f"(v) : "memory");
}
#define CLU_ARRIVE() asm volatile("barrier.cluster.arrive.aligned;" ::: "memory")
#define CLU_WAIT()   asm volatile("barrier.cluster.wait.aligned;"   ::: "memory")

// ===================== CLUSTER KERNEL: SMEM layout (floats) =================
#define O_WA    0        // 8*384   = 3072
#define O_WIH   3072     // 48*128  = 6144
#define O_WHH   9216     // 48*256  = 12288
#define O_BA    21504    // 8
#define O_BIH   21512    // 48
#define O_BHH   21560    // 48
#define O_HS    21608    // 128*33*2 = 8448   paired h: (k,b) -> ((k>>1)*33+b)*2+(k&1)
#define O_XTS   30056    // 4224
#define O_XWS   34280    // 4224
#define O_GISA  38504    // 48*33 = 1584
#define O_GISB  40088    // 1584
#define O_GHSA  41672    // 1584
#define O_GHSB  43256    // 1584
#define O_PSA   44840    // 8*33 = 264
#define O_PSB   45104    // 264
#define O_SCS   45368    // 32*133 = 4256  scores[b][row]
#define O_RED   49624    // 32
#define SMEM_FLOATS_CL 49656     // 198624 bytes

extern "C" __global__ void __launch_bounds__(NTHR)
da_rnn_cluster(const float* __restrict__ x,
               const float* __restrict__ W_a,  const float* __restrict__ b_a,
               const float* __restrict__ W_ih, const float* __restrict__ b_ih,
               const float* __restrict__ W_hh, const float* __restrict__ b_hh,
               const float* __restrict__ W_t,  const float* __restrict__ b_t,
               const float* __restrict__ W_f,  const float* __restrict__ b_f,
               float* __restrict__ out)
{
    extern __shared__ float sm[];
    float* Wa_s  = sm + O_WA;
    float* Wih_s = sm + O_WIH;
    float* Whh_s = sm + O_WHH;
    float* ba_s  = sm + O_BA;
    float* bih_s = sm + O_BIH;
    float* bhh_s = sm + O_BHH;
    float* hsf   = sm + O_HS;
    float* xtf   = sm + O_XTS;
    float* xwf   = sm + O_XWS;
    float* gisA  = sm + O_GISA;
    float* gisB  = sm + O_GISB;
    float* ghsA  = sm + O_GHSA;
    float* ghsB  = sm + O_GHSB;
    float* psA   = sm + O_PSA;
    float* psB   = sm + O_PSB;
    float* scs   = sm + O_SCS;
    float* red   = sm + O_RED;
    const u64* hs64 = (const u64*)hsf;
    const u64* xt64 = (const u64*)xtf;
    const u64* xw64 = (const u64*)xwf;

    const int tid  = threadIdx.x;
    const int grp  = blockIdx.x >> 4;
    uint32_t rr_u;
    asm("mov.u32 %0, %%cluster_ctarank;" : "=r"(rr_u));
    const int rr   = (int)rr_u;           // 0..15
    const int gb0  = grp * GB;
    const int lane = tid & 31;
    const int wrp  = tid >> 5;            // 0..15
    const uint32_t smb = smem_u32(sm);    // u32 base of dynamic smem

    // ---- load weight slice into SMEM (once) ----
    for (int i = tid; i < 8 * 384; i += NTHR)
        Wa_s[i] = W_a[3072 * rr + i];
    for (int i = tid; i < 48 * 128; i += NTHR) {
        int l = i >> 7, k = i & 127;
        int grow = (l >> 4) * Hq + 16 * rr + (l & 15);
        Wih_s[i] = W_ih[grow * Iq + k];
    }
    for (int i = tid; i < 48 * 256; i += NTHR) {
        int l = i >> 8, k = i & 255;
        int grow = (l >> 4) * Hq + 16 * rr + (l & 15);
        Whh_s[i] = W_hh[grow * Hq + k];
    }
    if (tid < 8) ba_s[tid] = b_a[8 * rr + tid];
    if (tid < 48) {
        int grow = (tid >> 4) * Hq + 16 * rr + (tid & 15);
        bih_s[tid] = b_ih[grow];
        bhh_s[tid] = b_hh[grow];
    }

    // ================= recurrent loop =================
    // barrier.cluster sequence per thread: [wait(h)] arrive(sc) wait(sc) arrive(h)
    for (int t = 0; t < Sq; t++) {
        // ---- stage x_t (no dep on h) ----
        for (int i = tid; i < Iq * GB; i += NTHR) {
            int b = i >> 7, k = i & 127;
            xtf[((k >> 1) * 33 + b) * 2 + (k & 1)] = x[((size_t)(gb0 + b) * Sq + t) * Iq + k];
        }
        if (t == 0) {
            for (int i = tid; i < 128 * 33 * 2; i += NTHR) hsf[i] = 0.f;
        } else {
            CLU_WAIT();                         // h(t-1) pushes from all ranks complete
        }
        __syncthreads();

        // ---- P1: warp-pair K-split. pair (w, w+8): score row w + gh rows 6w..6w+5 ----
        {
            const int w = wrp & 7, half = wrp >> 3;
            const int R = 6 * w;
            const u64* wax = (const u64*)(Wa_s + w * 384);   // x-part weights (64 u64)
            const u64* wah = wax + 64;                        // h-part weights (128 u64)
            const u64* wg  = (const u64*)(Whh_s + R * Hq);    // 6 rows, stride 128 u64
            u64 sacc = 0ull, a0 = 0ull, a1 = 0ull, a2 = 0ull, a3 = 0ull, a4 = 0ull, a5 = 0ull;

            const int kx = half * 32;
            #pragma unroll 4
            for (int k2 = kx; k2 < kx + 32; k2 += 2) {
                u64 x0 = xt64[k2 * 33 + lane];
                u64 x1 = xt64[(k2 + 1) * 33 + lane];
                ulonglong2 wv = *(const ulonglong2*)(wax + k2);
                fma2(sacc, wv.x, x0); fma2(sacc, wv.y, x1);
            }
            const int kh = half * 64;
            #pragma unroll 2
            for (int k2 = kh; k2 < kh + 64; k2 += 2) {
                u64 h0 = hs64[k2 * 33 + lane];
                u64 h1 = hs64[(k2 + 1) * 33 + lane];
                ulonglong2 wv;
                wv = *(const ulonglong2*)(wah + k2);       fma2(sacc, wv.x, h0); fma2(sacc, wv.y, h1);
                wv = *(const ulonglong2*)(wg + k2);        fma2(a0, wv.x, h0);   fma2(a0, wv.y, h1);
                wv = *(const ulonglong2*)(wg + 128 + k2);  fma2(a1, wv.x, h0);   fma2(a1, wv.y, h1);
                wv = *(const ulonglong2*)(wg + 256 + k2);  fma2(a2, wv.x, h0);   fma2(a2, wv.y, h1);
                wv = *(const ulonglong2*)(wg + 384 + k2);  fma2(a3, wv.x, h0);   fma2(a3, wv.y, h1);
                wv = *(const ulonglong2*)(wg + 512 + k2);  fma2(a4, wv.x, h0);   fma2(a4, wv.y, h1);
                wv = *(const ulonglong2*)(wg + 640 + k2);  fma2(a5, wv.x, h0);   fma2(a5, wv.y, h1);
            }
            float* gX = half ? ghsB : ghsA;
            float bs  = half ? 0.f : 1.f;
            gX[(R + 0) * 33 + lane] = f2sum(a0, bs * bhh_s[R + 0]);
            gX[(R + 1) * 33 + lane] = f2sum(a1, bs * bhh_s[R + 1]);
            gX[(R + 2) * 33 + lane] = f2sum(a2, bs * bhh_s[R + 2]);
            gX[(R + 3) * 33 + lane] = f2sum(a3, bs * bhh_s[R + 3]);
            gX[(R + 4) * 33 + lane] = f2sum(a4, bs * bhh_s[R + 4]);
            gX[(R + 5) * 33 + lane] = f2sum(a5, bs * bhh_s[R + 5]);
            float* pX = half ? psB : psA;
            pX[w * 33 + lane] = f2sum(sacc, 0.f);
        }
        __syncthreads();

        // ---- finalize scores + push to all ranks (row w; halves split rank range) ----
        {
            const int w = wrp & 7, half = wrp >> 3;
            float s = ftanh(psA[w * 33 + lane] + psB[w * 33 + lane] + ba_s[w]);
            uint32_t soff = smb + (uint32_t)((O_SCS + lane * 133 + 8 * rr + w) * 4);
            const int r0 = 8 * half;
            #pragma unroll
            for (int r = r0; r < r0 + 8; r++) push_b32(soff, r, s);
        }
        CLU_ARRIVE();                               // release score pushes
        CLU_WAIT();                                 // all scores present in scs

        // ---- P2: softmax + xw for all 32 batches (local, from scs) ----
        #pragma unroll
        for (int bi = 0; bi < 2; bi++) {
            int b = 2 * wrp + bi;
            const float* sp = scs + b * 133;
            float e0 = __expf(sp[lane]);
            float e1 = __expf(sp[lane + 32]);
            float e2 = __expf(sp[lane + 64]);
            float e3 = __expf(sp[lane + 96]);
            float s = e0 + e1 + e2 + e3;
            #pragma unroll
            for (int off = 16; off; off >>= 1) s += __shfl_xor_sync(0xffffffffu, s, off);
            float inv = 1.f / s;
            int k = lane;
            xwf[((k >> 1) * 33 + b) * 2 + (k & 1)] = e0 * inv * xtf[((k >> 1) * 33 + b) * 2 + (k & 1)];
            k = lane + 32;
            xwf[((k >> 1) * 33 + b) * 2 + (k & 1)] = e1 * inv * xtf[((k >> 1) * 33 + b) * 2 + (k & 1)];
            k = lane + 64;
            xwf[((k >> 1) * 33 + b) * 2 + (k & 1)] = e2 * inv * xtf[((k >> 1) * 33 + b) * 2 + (k & 1)];
            k = lane + 96;
            xwf[((k >> 1) * 33 + b) * 2 + (k & 1)] = e3 * inv * xtf[((k >> 1) * 33 + b) * 2 + (k & 1)];
        }
        __syncthreads();

        // ---- P3: gi, warp-pair K-split (rows 6w..6w+5, k-half per warp) ----
        {
            const int w = wrp & 7, half = wrp >> 3;
            const int R = 6 * w;
            const u64* wg = (const u64*)(Wih_s + R * Iq);   // stride 64 u64 per row
            u64 a0 = 0ull, a1 = 0ull, a2 = 0ull, a3 = 0ull, a4 = 0ull, a5 = 0ull;
            const int k0 = half * 32;
            #pragma unroll 4
            for (int k2 = k0; k2 < k0 + 32; k2 += 2) {
                u64 x0 = xw64[k2 * 33 + lane];
                u64 x1 = xw64[(k2 + 1) * 33 + lane];
                ulonglong2 wv;
                wv = *(const ulonglong2*)(wg + k2);        fma2(a0, wv.x, x0); fma2(a0, wv.y, x1);
                wv = *(const ulonglong2*)(wg + 64 + k2);   fma2(a1, wv.x, x0); fma2(a1, wv.y, x1);
                wv = *(const ulonglong2*)(wg + 128 + k2);  fma2(a2, wv.x, x0); fma2(a2, wv.y, x1);
                wv = *(const ulonglong2*)(wg + 192 + k2);  fma2(a3, wv.x, x0); fma2(a3, wv.y, x1);
                wv = *(const ulonglong2*)(wg + 256 + k2);  fma2(a4, wv.x, x0); fma2(a4, wv.y, x1);
                wv = *(const ulonglong2*)(wg + 320 + k2);  fma2(a5, wv.x, x0); fma2(a5, wv.y, x1);
            }
            float* gX = half ? gisB : gisA;
            float bs  = half ? 0.f : 1.f;
            gX[(R + 0) * 33 + lane] = f2sum(a0, bs * bih_s[R + 0]);
            gX[(R + 1) * 33 + lane] = f2sum(a1, bs * bih_s[R + 1]);
            gX[(R + 2) * 33 + lane] = f2sum(a2, bs * bih_s[R + 2]);
            gX[(R + 3) * 33 + lane] = f2sum(a3, bs * bih_s[R + 3]);
            gX[(R + 4) * 33 + lane] = f2sum(a4, bs * bih_s[R + 4]);
            gX[(R + 5) * 33 + lane] = f2sum(a5, bs * bih_s[R + 5]);
        }
        __syncthreads();

        // ---- gates + h push (2 units/thread; halves split the rank push range) ----
        {
            const int tt = tid & 255;
            const int half = tid >> 8;
            const int u2 = tt & 7;            // unit pair 2u2, 2u2+1
            const int b  = tt >> 3;           // 0..31
            const int u0 = 2 * u2, u1 = u0 + 1;

            float gi_r0 = gisA[u0 * 33 + b] + gisB[u0 * 33 + b];
            float gh_r0 = ghsA[u0 * 33 + b] + ghsB[u0 * 33 + b];
            float gi_z0 = gisA[(16 + u0) * 33 + b] + gisB[(16 + u0) * 33 + b];
            float gh_z0 = ghsA[(16 + u0) * 33 + b] + ghsB[(16 + u0) * 33 + b];
            float gi_n0 = gisA[(32 + u0) * 33 + b] + gisB[(32 + u0) * 33 + b];
            float gh_n0 = ghsA[(32 + u0) * 33 + b] + ghsB[(32 + u0) * 33 + b];
            float gi_r1 = gisA[u1 * 33 + b] + gisB[u1 * 33 + b];
            float gh_r1 = ghsA[u1 * 33 + b] + ghsB[u1 * 33 + b];
            float gi_z1 = gisA[(16 + u1) * 33 + b] + gisB[(16 + u1) * 33 + b];
            float gh_z1 = ghsA[(16 + u1) * 33 + b] + ghsB[(16 + u1) * 33 + b];
            float gi_n1 = gisA[(32 + u1) * 33 + b] + gisB[(32 + u1) * 33 + b];
            float gh_n1 = ghsA[(32 + u1) * 33 + b] + ghsB[(32 + u1) * 33 + b];

            const int hidx = ((8 * rr + u2) * 33 + b) * 2;   // paired slot (even k)
            float hp0 = hsf[hidx], hp1 = hsf[hidx + 1];

            float r0 = fsig(gi_r0 + gh_r0);
            float z0 = fsig(gi_z0 + gh_z0);
            float n0 = ftanh(gi_n0 + r0 * gh_n0);
            float hn0 = (1.f - z0) * n0 + z0 * hp0;
            float r1 = fsig(gi_r1 + gh_r1);
            float z1 = fsig(gi_z1 + gh_z1);
            float n1 = ftanh(gi_n1 + r1 * gh_n1);
            float hn1 = (1.f - z1) * n1 + z1 * hp1;

            __syncthreads();   // everyone read hp (h(t-1)) before any self-push lands

            u64 pk;
            asm("mov.b64 %0, {%1,%2};" : "=l"(pk) : "f"(hn0), "f"(hn1));
            uint32_t hoff = smb + (uint32_t)((O_HS + hidx) * 4);
            const int r0k = 8 * half;
            #pragma unroll
            for (int r = r0k; r < r0k + 8; r++) push_b64(hoff, r, pk);

            if (half == 0) {
                float2 st; st.x = hn0; st.y = hn1;
                *(float2*)&d_enc[((size_t)t * Bq + gb0 + b) * Hq + 16 * rr + u0] = st;
            }
        }
        CLU_ARRIVE();                                // release h pushes + d_enc stores
    }
    CLU_WAIT();                                      // match final arrive; all d_enc done
    __threadfence();                                 // invalidate own L1 before d_enc reads
    __syncthreads();

    // ================= temporal attention + FC (2 batches/CTA) =================
    float* wts = xtf;     // 256 floats
    float* ess = gisA;    // 512 floats
    float* prt = ghsA;    // 512 floats
    if (tid < Hq) wts[tid] = W_t[tid];
    const float btv = b_t[0];
    const float bfv = b_f[0];
    __syncthreads();

    for (int bi = 0; bi < 2; bi++) {
        int bb = gb0 + 2 * rr + bi;

        for (int tt = wrp; tt < Sq; tt += 16) {
            const float* er = d_enc + ((size_t)tt * Bq + bb) * Hq;
            float s = 0.f;
            #pragma unroll
            for (int j = 0; j < 8; j++) s += er[lane + 32 * j] * wts[lane + 32 * j];
            #pragma unroll
            for (int off = 16; off; off >>= 1) s += __shfl_xor_sync(0xffffffffu, s, off);
            if (lane == 0) ess[tt] = __expf(ftanh(s + btv));
        }
        __syncthreads();

        float pp = ess[tid];
        #pragma unroll
        for (int off = 16; off; off >>= 1) pp += __shfl_xor_sync(0xffffffffu, pp, off);
        if (lane == 0) red[wrp] = pp;
        __syncthreads();
        float denom = 0.f;
        #pragma unroll
        for (int j = 0; j < 16; j++) denom += red[j];

        {
            int h = tid & 255, half = tid >> 8;
            const float* eb = d_enc + ((size_t)(half * 256) * Bq + bb) * Hq + h;
            const float* ep = ess + half * 256;
            float acc = 0.f;
            #pragma unroll 4
            for (int tt = 0; tt < 256; tt++)
                acc += ep[tt] * eb[(size_t)tt * Bq * Hq];
            prt[tid] = acc;
        }
        __syncthreads();

        if (tid < Hq) {
            float ctx = (prt[tid] + prt[tid + 256]) / denom;
            float part = ctx * W_f[tid];
            #pragma unroll
            for (int off = 16; off; off >>= 1) part += __shfl_xor_sync(0xffffffffu, part, off);
            if (lane == 0) red[16 + wrp] = part;
        }
        __syncthreads();
        if (tid == 0) {
            float lg = bfv;
            #pragma unroll
            for (int j = 0; j < 8; j++) lg += red[16 + j];
            out[bb] = 1.f / (1.f + __expf(-lg));
        }
        __syncthreads();
    }
}

// ===================== FALLBACK (proven R7 kernel, L2 barriers) =============
#define F_WA   0
#define F_WIH  3072
#define F_WHH  9216
#define F_BA   21504
#define F_BIH  21512
#define F_BHH  21560
#define F_HS   21608
#define F_XTS  30056
#define F_XWS  34280
#define F_GIS  38504
#define F_GHS  40088
#define F_RED  41672
#define SMEM_FLOATS_FB 41704

__device__ __forceinline__ void group_barrier(int g, int& want) {
    __threadfence();
    __syncthreads();
    if (threadIdx.x == 0) {
        want++;
        int old = atomicAdd(&g_cnt[g], 1);
        if (old == CPG - 1) {
            atomicExch(&g_cnt[g], 0);
            red_release_add(&g_phase[g], 1);
        } else {
            while (ld_acq(&g_phase[g]) < want) { }
        }
    }
    __syncthreads();
    __threadfence();
}

extern "C" __global__ void __launch_bounds__(NTHR)
da_rnn_fb(const float* __restrict__ x,
          const float* __restrict__ W_a,  const float* __restrict__ b_a,
          const float* __restrict__ W_ih, const float* __restrict__ b_ih,
          const float* __restrict__ W_hh, const float* __restrict__ b_hh,
          const float* __restrict__ W_t,  const float* __restrict__ b_t,
          const float* __restrict__ W_f,  const float* __restrict__ b_f,
          float* __restrict__ out)
{
    extern __shared__ float sm[];
    float* Wa_s  = sm + F_WA;
    float* Wih_s = sm + F_WIH;
    float* Whh_s = sm + F_WHH;
    float* ba_s  = sm + F_BA;
    float* bih_s = sm + F_BIH;
    float* bhh_s = sm + F_BHH;
    float* hsf   = sm + F_HS;
    float* xtf   = sm + F_XTS;
    float* xwf   = sm + F_XWS;
    float* gis   = sm + F_GIS;
    float* ghs   = sm + F_GHS;
    float* red   = sm + F_RED;
    const u64* hs64 = (const u64*)hsf;
    const u64* xt64 = (const u64*)xtf;
    const u64* xw64 = (const u64*)xwf;

    const int tid  = threadIdx.x;
    const int grp  = blockIdx.x >> 4;
    const int rr   = blockIdx.x & 15;
    const int gb0  = grp * GB;
    const int lane = tid & 31;
    const int wrp  = tid >> 5;

    for (int i = tid; i < 8 * 384; i += NTHR)
        Wa_s[i] = W_a[3072 * rr + i];
    for (int i = tid; i < 48 * 128; i += NTHR) {
        int l = i >> 7, k = i & 127;
        int grow = (l >> 4) * Hq + 16 * rr + (l & 15);
        Wih_s[i] = W_ih[grow * Iq + k];
    }
    for (int i = tid; i < 48 * 256; i += NTHR) {
        int l = i >> 8, k = i & 255;
        int grow = (l >> 4) * Hq + 16 * rr + (l & 15);
        Whh_s[i] = W_hh[grow * Hq + k];
    }
    if (tid < 8) ba_s[tid] = b_a[8 * rr + tid];
    if (tid < 48) {
        int grow = (tid >> 4) * Hq + 16 * rr + (tid & 15);
        bih_s[tid] = b_ih[grow];
        bhh_s[tid] = b_hh[grow];
    }

    int want = 0;
    if (tid == 0) want = ld_acq(&g_phase[grp]);
    __syncthreads();

    for (int t = 0; t < Sq; t++) {
        if (t == 0) {
            for (int i = tid; i < Hq * GB; i += NTHR) {
                int b = i >> 8, u = i & 255;
                hsf[((u >> 1) * 33 + b) * 2 + (u & 1)] = 0.f;
            }
        } else {
            const float* ep = d_enc + (size_t)(t - 1) * Bq * Hq + (size_t)gb0 * Hq;
            for (int i = tid; i < Hq * GB; i += NTHR) {
                int b = i >> 8, u = i & 255;
                hsf[((u >> 1) * 33 + b) * 2 + (u & 1)] = ep[b * Hq + u];
            }
        }
        for (int i = tid; i < Iq * GB; i += NTHR) {
            int b = i >> 7, k = i & 127;
            xtf[((k >> 1) * 33 + b) * 2 + (k & 1)] = x[((size_t)(gb0 + b) * Sq + t) * Iq + k];
        }
        __syncthreads();

        if (wrp < 8) {
            const int srow = wrp;
            const int R = 2 * wrp;
            const u64* wax = (const u64*)(Wa_s + srow * 384);
            u64 sacc = 0ull;
            #pragma unroll 4
            for (int k2 = 0; k2 < 64; k2 += 2) {
                u64 x0 = xt64[k2 * 33 + lane];
                u64 x1 = xt64[(k2 + 1) * 33 + lane];
                ulonglong2 w = *(const ulonglong2*)(wax + k2);
                fma2(sacc, w.x, x0); fma2(sacc, w.y, x1);
            }
            const u64* wah = wax + 64;
            const u64* wg0 = (const u64*)(Whh_s + R * Hq);
            const u64* wg1 = wg0 + 128;
            u64 a0 = 0ull, a1 = 0ull;
            #pragma unroll 2
            for (int k2 = 0; k2 < 128; k2 += 2) {
                u64 h0 = hs64[k2 * 33 + lane];
                u64 h1 = hs64[(k2 + 1) * 33 + lane];
                ulonglong2 wa = *(const ulonglong2*)(wah + k2);
                fma2(sacc, wa.x, h0); fma2(sacc, wa.y, h1);
                ulonglong2 w0 = *(const ulonglong2*)(wg0 + k2);
                fma2(a0, w0.x, h0); fma2(a0, w0.y, h1);
                ulonglong2 w1 = *(const ulonglong2*)(wg1 + k2);
                fma2(a1, w1.x, h0); fma2(a1, w1.y, h1);
            }
            d_scores[(gb0 + lane) * Iq + 8 * rr + srow] = tanhf(f2sum(sacc, ba_s[srow]));
            ghs[R * 33 + lane]       = f2sum(a0, bhh_s[R]);
            ghs[(R + 1) * 33 + lane] = f2sum(a1, bhh_s[R + 1]);
        } else {
            const int R = 16 + 4 * (wrp - 8);
            const u64* w0 = (const u64*)(Whh_s + R * Hq);
            const u64* w1 = w0 + 128;
            const u64* w2 = w0 + 256;
            const u64* w3 = w0 + 384;
            u64 a0 = 0ull, a1 = 0ull, a2 = 0ull, a3 = 0ull;
            #pragma unroll 2
            for (int k2 = 0; k2 < 128; k2 += 2) {
                u64 h0 = hs64[k2 * 33 + lane];
                u64 h1 = hs64[(k2 + 1) * 33 + lane];
                ulonglong2 v0 = *(const ulonglong2*)(w0 + k2);
                fma2(a0, v0.x, h0); fma2(a0, v0.y, h1);
                ulonglong2 v1 = *(const ulonglong2*)(w1 + k2);
                fma2(a1, v1.x, h0); fma2(a1, v1.y, h1);
                ulonglong2 v2 = *(const ulonglong2*)(w2 + k2);
                fma2(a2, v2.x, h0); fma2(a2, v2.y, h1);
                ulonglong2 v3 = *(const ulonglong2*)(w3 + k2);
                fma2(a3, v3.x, h0); fma2(a3, v3.y, h1);
            }
            ghs[R * 33 + lane]       = f2sum(a0, bhh_s[R]);
            ghs[(R + 1) * 33 + lane] = f2sum(a1, bhh_s[R + 1]);
            ghs[(R + 2) * 33 + lane] = f2sum(a2, bhh_s[R + 2]);
            ghs[(R + 3) * 33 + lane] = f2sum(a3, bhh_s[R + 3]);
        }
        group_barrier(grp, want);

        #pragma unroll
        for (int bi = 0; bi < 2; bi++) {
            int b = 2 * wrp + bi;
            const float* sp = d_scores + (size_t)(gb0 + b) * Iq;
            float e0 = expf(sp[lane]);
            float e1 = expf(sp[lane + 32]);
            float e2 = expf(sp[lane + 64]);
            float e3 = expf(sp[lane + 96]);
            float s = e0 + e1 + e2 + e3;
            #pragma unroll
            for (int off = 16; off; off >>= 1) s += __shfl_xor_sync(0xffffffffu, s, off);
            float inv = 1.f / s;
            int k = lane;
            xwf[((k >> 1) * 33 + b) * 2 + (k & 1)] = e0 * inv * xtf[((k >> 1) * 33 + b) * 2 + (k & 1)];
            k = lane + 32;
            xwf[((k >> 1) * 33 + b) * 2 + (k & 1)] = e1 * inv * xtf[((k >> 1) * 33 + b) * 2 + (k & 1)];
            k = lane + 64;
            xwf[((k >> 1) * 33 + b) * 2 + (k & 1)] = e2 * inv * xtf[((k >> 1) * 33 + b) * 2 + (k & 1)];
            k = lane + 96;
            xwf[((k >> 1) * 33 + b) * 2 + (k & 1)] = e3 * inv * xtf[((k >> 1) * 33 + b) * 2 + (k & 1)];
        }
        __syncthreads();

        {
            const int R = 3 * wrp;
            const u64* w0 = (const u64*)(Wih_s + R * Iq);
            const u64* w1 = w0 + 64;
            const u64* w2 = w0 + 128;
            u64 a0 = 0ull, a1 = 0ull, a2 = 0ull;
            #pragma unroll 4
            for (int k2 = 0; k2 < 64; k2 += 2) {
                u64 x0 = xw64[k2 * 33 + lane];
                u64 x1 = xw64[(k2 + 1) * 33 + lane];
                ulonglong2 v0 = *(const ulonglong2*)(w0 + k2);
                fma2(a0, v0.x, x0); fma2(a0, v0.y, x1);
                ulonglong2 v1 = *(const ulonglong2*)(w1 + k2);
                fma2(a1, v1.x, x0); fma2(a1, v1.y, x1);
                ulonglong2 v2 = *(const ulonglong2*)(w2 + k2);
                fma2(a2, v2.x, x0); fma2(a2, v2.y, x1);
            }
            gis[R * 33 + lane]       = f2sum(a0, bih_s[R]);
            gis[(R + 1) * 33 + lane] = f2sum(a1, bih_s[R + 1]);
            gis[(R + 2) * 33 + lane] = f2sum(a2, bih_s[R + 2]);
        }
        __syncthreads();

        {
            int u = tid & 15;
            int b = tid >> 4;
            float r = fsig(gis[u * 33 + b] + ghs[u * 33 + b]);
            float z = fsig(gis[(16 + u) * 33 + b] + ghs[(16 + u) * 33 + b]);
            float n = tanhf(gis[(32 + u) * 33 + b] + r * ghs[(32 + u) * 33 + b]);
            int ug = 16 * rr + u;
            float hp = hsf[((ug >> 1) * 33 + b) * 2 + (ug & 1)];
            float hn = (1.f - z) * n + z * hp;
            d_enc[((size_t)t * Bq + gb0 + b) * Hq + ug] = hn;
        }
        group_barrier(grp, want);
    }

    float* wts = xtf;
    float* ess = gis;
    float* prt = ghs;
    if (tid < Hq) wts[tid] = W_t[tid];
    const float btv = b_t[0];
    const float bfv = b_f[0];
    __syncthreads();

    for (int bi = 0; bi < 2; bi++) {
        int bb = gb0 + 2 * rr + bi;
        for (int tt = wrp; tt < Sq; tt += 16) {
            const float* er = d_enc + ((size_t)tt * Bq + bb) * Hq;
            float s = 0.f;
            #pragma unroll
            for (int j = 0; j < 8; j++) s += er[lane + 32 * j] * wts[lane + 32 * j];
            #pragma unroll
            for (int off = 16; off; off >>= 1) s += __shfl_xor_sync(0xffffffffu, s, off);
            if (lane == 0) ess[tt] = expf(tanhf(s + btv));
        }
        __syncthreads();
        float pp = ess[tid];
        #pragma unroll
        for (int off = 16; off; off >>= 1) pp += __shfl_xor_sync(0xffffffffu, pp, off);
        if (lane == 0) red[wrp] = pp;
        __syncthreads();
        float denom = 0.f;
        #pragma unroll
        for (int j = 0; j < 16; j++) denom += red[j];
        {
            int h = tid & 255, half = tid >> 8;
            const float* eb = d_enc + ((size_t)(half * 256) * Bq + bb) * Hq + h;
            const float* ep = ess + half * 256;
            float acc = 0.f;
            #pragma unroll 4
            for (int tt = 0; tt < 256; tt++)
                acc += ep[tt] * eb[(size_t)tt * Bq * Hq];
            prt[tid] = acc;
        }
        __syncthreads();
        if (tid < Hq) {
            float ctx = (prt[tid] + prt[tid + 256]) / denom;
            float part = ctx * W_f[tid];
            #pragma unroll
            for (int off = 16; off; off >>= 1) part += __shfl_xor_sync(0xffffffffu, part, off);
            if (lane == 0) red[16 + wrp] = part;
        }
        __syncthreads();
        if (tid == 0) {
            float lg = bfv;
            #pragma unroll
            for (int j = 0; j < 8; j++) lg += red[16 + j];
            out[bb] = 1.f / (1.f + expf(-lg));
        }
        __syncthreads();
    }
}

// ================================ launch ====================================
extern "C" void kernel_launch(void* const* d_in, const int* in_sizes, int n_in,
                              void* d_out, int out_size)
{
    const float* x    = (const float*)d_in[0];
    const float* W_a  = (const float*)d_in[1];
    const float* b_a  = (const float*)d_in[2];
    const float* W_ih = (const float*)d_in[3];
    const float* b_ih = (const float*)d_in[4];
    const float* W_hh = (const float*)d_in[5];
    const float* b_hh = (const float*)d_in[6];
    const float* W_t  = (const float*)d_in[7];
    const float* b_t  = (const float*)d_in[8];
    const float* W_f  = (const float*)d_in[9];
    const float* b_f  = (const float*)d_in[10];
    float* out = (float*)d_out;

    const size_t smem_cl = (size_t)SMEM_FLOATS_CL * sizeof(float);   // 198624
    cudaFuncSetAttribute(da_rnn_cluster, cudaFuncAttributeMaxDynamicSharedMemorySize,
                         (int)smem_cl);
    cudaFuncSetAttribute(da_rnn_cluster, cudaFuncAttributeNonPortableClusterSizeAllowed, 1);

    cudaLaunchConfig_t cfg = {};
    cfg.gridDim  = dim3(NCTA, 1, 1);
    cfg.blockDim = dim3(NTHR, 1, 1);
    cfg.dynamicSmemBytes = smem_cl;
    cfg.stream = 0;
    cudaLaunchAttribute attrs[1];
    attrs[0].id = cudaLaunchAttributeClusterDimension;
    attrs[0].val.clusterDim.x = CPG;
    attrs[0].val.clusterDim.y = 1;
    attrs[0].val.clusterDim.z = 1;
    cfg.attrs = attrs;
    cfg.numAttrs = 1;

    int nclu = 0;
    cudaError_t qe = cudaOccupancyMaxActiveClusters(&nclu, da_rnn_cluster, &cfg);
    if (qe == cudaSuccess && nclu >= NGRP) {
        cudaLaunchKernelEx(&cfg, da_rnn_cluster, x, W_a, b_a, W_ih, b_ih, W_hh, b_hh,
                           W_t, b_t, W_f, b_f, out);
    } else {
        (void)cudaGetLastError();   // clear query error, take fallback path
        const size_t smem_fb = (size_t)SMEM_FLOATS_FB * sizeof(float);
        cudaFuncSetAttribute(da_rnn_fb, cudaFuncAttributeMaxDynamicSharedMemorySize,
                             (int)smem_fb);
        da_rnn_fb<<<NCTA, NTHR, smem_fb>>>(x, W_a, b_a, W_ih, b_ih, W_hh, b_hh,
                                           W_t, b_t, W_f, b_f, out);
    }
}